// round 17
// baseline (speedup 1.0000x reference)
#include <cuda_runtime.h>
#include <math.h>

// ---------------------------------------------------------------------------
// SoftCluster_adaptiveK — round 17 (= R16, iteration kernel at 320 thr with
// 3-row interleave: concurrency/SMSP 6 -> 7.5 chains, regs ~160 < 204 cap)
// ---------------------------------------------------------------------------

#define D      256
#define KMAX   6
#define GRID1  148
#define T1     320
#define NW1    (T1 / 32)
#define DB     592
#define TM     256
#define TOLV   1e-5
#define ESHIFT 24.0f
#define FPAD   8
#define OFFL   56

typedef unsigned long long u64;

// ---- device scratch (static; no allocation anywhere) ----
__device__ float  g_centers[KMAX * D];
__device__ float  g_prev[KMAX * D];
__device__ float  g_csq[KMAX];
__device__ float  g_w[KMAX];
__device__ float  g_P[GRID1 * KMAX * D];
__device__ float  g_Pc[GRID1 * KMAX];
__device__ double g_shiftp[KMAX];
__device__ float  g_dmin[131072];
__device__ float  g_xsq[131072];
__device__ double g_bsum[DB];
__device__ int    g_flag_main[GRID1 * FPAD];
__device__ int    g_flag_upd[KMAX * FPAD];
__device__ int    g_maxiters;
__device__ int    g_idx;

// ---- helpers ----
__device__ __forceinline__ u64 pk2(float lo, float hi) {
    u64 r; asm("mov.b64 %0,{%1,%2};" : "=l"(r) : "f"(lo), "f"(hi)); return r;
}
__device__ __forceinline__ void upk2(u64 v, float& lo, float& hi) {
    asm("mov.b64 {%0,%1},%2;" : "=f"(lo), "=f"(hi) : "l"(v));
}
__device__ __forceinline__ u64 fma2(u64 a, u64 b, u64 c) {
    u64 r; asm("fma.rn.f32x2 %0,%1,%2,%3;" : "=l"(r) : "l"(a), "l"(b), "l"(c)); return r;
}
__device__ __forceinline__ u64 mul2(u64 a, u64 b) {
    u64 r; asm("mul.rn.f32x2 %0,%1,%2;" : "=l"(r) : "l"(a), "l"(b)); return r;
}
__device__ __forceinline__ float wsum(float v) {
    #pragma unroll
    for (int m = 16; m; m >>= 1) v += __shfl_xor_sync(0xffffffffu, v, m);
    return v;
}
__device__ __forceinline__ float dot4(float4 a, float4 b) {
    return a.x * b.x + a.y * b.y + a.z * b.z + a.w * b.w;
}
__device__ __forceinline__ int ld_cg_i32(const int* p) {
    int v; asm volatile("ld.global.cg.b32 %0, [%1];" : "=r"(v) : "l"(p)); return v;
}
__device__ __forceinline__ void st_cg_i32(int* p, int v) {
    asm volatile("st.global.cg.b32 [%0], %1;" :: "l"(p), "r"(v) : "memory");
}

// ---------------------------------------------------------------------------
__global__ void k_init(const float* __restrict__ x,
                       const float* __restrict__ logits,
                       const float* __restrict__ gumbel,
                       const float* __restrict__ uinit,
                       const int*   __restrict__ maxit,
                       int N) {
    __shared__ double s_sq[256];
    int tid = threadIdx.x;
    if (tid == 0) {
        g_maxiters = maxit[0];
        float l[KMAX]; float m = -3.4e38f;
        for (int j = 0; j < KMAX; j++) { l[j] = logits[j] + gumbel[j]; m = fmaxf(m, l[j]); }
        float s = 0.f, e[KMAX];
        for (int j = 0; j < KMAX; j++) { e[j] = expf(l[j] - m); s += e[j]; }
        for (int j = 0; j < KMAX; j++) g_w[j] = e[j] / s;
        float f = uinit[0] * (float)N;
        int idx = (int)f;
        if (idx > N - 1) idx = N - 1;
        if (idx < 0) idx = 0;
        g_idx = idx;
    }
    for (int i = tid; i < KMAX * D; i += blockDim.x) g_prev[i] = 0.f;
    for (int i = tid; i < GRID1 * FPAD; i += blockDim.x) g_flag_main[i] = 0;
    for (int i = tid; i < KMAX * FPAD; i += blockDim.x) g_flag_upd[i] = 0;
    __syncthreads();
    int idx = g_idx;
    float v = x[(size_t)idx * D + tid];
    g_centers[tid] = v;
    s_sq[tid] = (double)v * (double)v;
    __syncthreads();
    for (int s = 128; s; s >>= 1) {
        if (tid < s) s_sq[tid] += s_sq[tid + s];
        __syncthreads();
    }
    if (tid == 0) g_csq[0] = (float)s_sq[0];
}

// ---------------------------------------------------------------------------
// xsq only (used when k == 1)
// ---------------------------------------------------------------------------
__global__ void __launch_bounds__(TM) k_xsq(const float* __restrict__ x, int N) {
    int tid = threadIdx.x;
    int lane = tid & 31;
    int gwarp = blockIdx.x * (TM / 32) + (tid >> 5);
    int tot = DB * (TM / 32);
    for (int row = gwarp; row < N; row += tot) {
        const float4* xr = (const float4*)x + (size_t)row * (D / 4);
        float4 a0 = __ldg(xr + lane);
        float4 a1 = __ldg(xr + lane + 32);
        float xs = wsum(dot4(a0, a0) + dot4(a1, a1));
        if (lane == 0) g_xsq[row] = xs;
    }
}

// ---------------------------------------------------------------------------
// k-means++ pass over CONTIGUOUS chunk, 4-row interleaved.
// Pass 1 (i==1) also computes and stores xsq.
// ---------------------------------------------------------------------------
__global__ void __launch_bounds__(TM) k_dmin(const float* __restrict__ x, int N, int i) {
    __shared__ float  s_c[D];
    __shared__ float  s_cs;
    __shared__ double s_ws[TM / 32];
    int tid = threadIdx.x;
    if (tid < D) s_c[tid] = g_centers[(i - 1) * D + tid];
    if (tid == 0) s_cs = g_csq[i - 1];
    if (tid < TM / 32) s_ws[tid] = 0.0;
    __syncthreads();
    int lane = tid & 31;
    int warp = tid >> 5;
    const int STEP = TM / 32;
    int chunk = (N + DB - 1) / DB;
    int st = blockIdx.x * chunk;
    int en = min(st + chunk, N);
    const float4* c4 = (const float4*)s_c;
    float4 c0 = c4[lane], c1 = c4[lane + 32];
    double wsumd = 0.0;

    int row = st + warp;
    while (row + 3 * STEP < en) {
        int r0 = row, r1 = row + STEP, r2 = row + 2 * STEP, r3 = row + 3 * STEP;
        const float4* x0 = (const float4*)x + (size_t)r0 * (D / 4);
        const float4* x1 = (const float4*)x + (size_t)r1 * (D / 4);
        const float4* x2 = (const float4*)x + (size_t)r2 * (D / 4);
        const float4* x3 = (const float4*)x + (size_t)r3 * (D / 4);
        float4 a00 = __ldg(x0 + lane),      a10 = __ldg(x1 + lane);
        float4 a20 = __ldg(x2 + lane),      a30 = __ldg(x3 + lane);
        float4 a01 = __ldg(x0 + lane + 32), a11 = __ldg(x1 + lane + 32);
        float4 a21 = __ldg(x2 + lane + 32), a31 = __ldg(x3 + lane + 32);
        float dp0 = dot4(a00, c0) + dot4(a01, c1);
        float dp1 = dot4(a10, c0) + dot4(a11, c1);
        float dp2 = dot4(a20, c0) + dot4(a21, c1);
        float dp3 = dot4(a30, c0) + dot4(a31, c1);
        if (i == 1) {
            float xs0 = dot4(a00, a00) + dot4(a01, a01);
            float xs1 = dot4(a10, a10) + dot4(a11, a11);
            float xs2 = dot4(a20, a20) + dot4(a21, a21);
            float xs3 = dot4(a30, a30) + dot4(a31, a31);
            #pragma unroll
            for (int m = 16; m; m >>= 1) {
                dp0 += __shfl_xor_sync(0xffffffffu, dp0, m);
                dp1 += __shfl_xor_sync(0xffffffffu, dp1, m);
                dp2 += __shfl_xor_sync(0xffffffffu, dp2, m);
                dp3 += __shfl_xor_sync(0xffffffffu, dp3, m);
                xs0 += __shfl_xor_sync(0xffffffffu, xs0, m);
                xs1 += __shfl_xor_sync(0xffffffffu, xs1, m);
                xs2 += __shfl_xor_sync(0xffffffffu, xs2, m);
                xs3 += __shfl_xor_sync(0xffffffffu, xs3, m);
            }
            if (lane == 0) {
                g_xsq[r0] = xs0; g_xsq[r1] = xs1; g_xsq[r2] = xs2; g_xsq[r3] = xs3;
                float d0 = sqrtf(fmaxf(xs0 + s_cs - 2.f * dp0, 1e-12f));
                float d1 = sqrtf(fmaxf(xs1 + s_cs - 2.f * dp1, 1e-12f));
                float d2 = sqrtf(fmaxf(xs2 + s_cs - 2.f * dp2, 1e-12f));
                float d3 = sqrtf(fmaxf(xs3 + s_cs - 2.f * dp3, 1e-12f));
                g_dmin[r0] = d0; g_dmin[r1] = d1; g_dmin[r2] = d2; g_dmin[r3] = d3;
                wsumd += ((double)d0 + (double)d1) + ((double)d2 + (double)d3);
            }
        } else {
            #pragma unroll
            for (int m = 16; m; m >>= 1) {
                dp0 += __shfl_xor_sync(0xffffffffu, dp0, m);
                dp1 += __shfl_xor_sync(0xffffffffu, dp1, m);
                dp2 += __shfl_xor_sync(0xffffffffu, dp2, m);
                dp3 += __shfl_xor_sync(0xffffffffu, dp3, m);
            }
            if (lane == 0) {
                float d0 = sqrtf(fmaxf(g_xsq[r0] + s_cs - 2.f * dp0, 1e-12f));
                float d1 = sqrtf(fmaxf(g_xsq[r1] + s_cs - 2.f * dp1, 1e-12f));
                float d2 = sqrtf(fmaxf(g_xsq[r2] + s_cs - 2.f * dp2, 1e-12f));
                float d3 = sqrtf(fmaxf(g_xsq[r3] + s_cs - 2.f * dp3, 1e-12f));
                float n0 = fminf(g_dmin[r0], d0);
                float n1 = fminf(g_dmin[r1], d1);
                float n2 = fminf(g_dmin[r2], d2);
                float n3 = fminf(g_dmin[r3], d3);
                g_dmin[r0] = n0; g_dmin[r1] = n1; g_dmin[r2] = n2; g_dmin[r3] = n3;
                wsumd += ((double)n0 + (double)n1) + ((double)n2 + (double)n3);
            }
        }
        row += 4 * STEP;
    }
    while (row < en) {
        const float4* xr = (const float4*)x + (size_t)row * (D / 4);
        float4 a0 = __ldg(xr + lane);
        float4 a1 = __ldg(xr + lane + 32);
        float dp = dot4(a0, c0) + dot4(a1, c1);
        if (i == 1) {
            float xs = dot4(a0, a0) + dot4(a1, a1);
            #pragma unroll
            for (int m = 16; m; m >>= 1) {
                dp += __shfl_xor_sync(0xffffffffu, dp, m);
                xs += __shfl_xor_sync(0xffffffffu, xs, m);
            }
            if (lane == 0) {
                g_xsq[row] = xs;
                float d = sqrtf(fmaxf(xs + s_cs - 2.f * dp, 1e-12f));
                g_dmin[row] = d;
                wsumd += (double)d;
            }
        } else {
            dp = wsum(dp);
            if (lane == 0) {
                float d = sqrtf(fmaxf(g_xsq[row] + s_cs - 2.f * dp, 1e-12f));
                float nd = fminf(g_dmin[row], d);
                g_dmin[row] = nd;
                wsumd += (double)nd;
            }
        }
        row += STEP;
    }
    if (lane == 0) s_ws[warp] = wsumd;
    __syncthreads();
    if (tid == 0) {
        double s = 0.0;
        #pragma unroll
        for (int w = 0; w < TM / 32; w++) s += s_ws[w];
        g_bsum[blockIdx.x] = s;
    }
}

// ---------------------------------------------------------------------------
// k-means++ select: two-level warp-shuffle scans (1024 threads = 32 warps).
// ---------------------------------------------------------------------------
__global__ void k_select(const float* __restrict__ x,
                         const float* __restrict__ uinit,
                         int N, int i) {
    __shared__ double s_wtot[32];
    __shared__ double s_sq[256];
    __shared__ double s_base;
    __shared__ int    s_pick;
    int tid  = threadIdx.x;
    int lane = tid & 31;
    int warp = tid >> 5;
    int chunk = (N + DB - 1) / DB;

    double v = (tid < DB) ? g_bsum[tid] : 0.0;
    double s = v;
    #pragma unroll
    for (int off = 1; off < 32; off <<= 1) {
        double n = __shfl_up_sync(0xffffffffu, s, off);
        if (lane >= off) s += n;
    }
    if (lane == 31) s_wtot[warp] = s;
    __syncthreads();
    if (warp == 0) {
        double t = s_wtot[lane];
        #pragma unroll
        for (int off = 1; off < 32; off <<= 1) {
            double n = __shfl_up_sync(0xffffffffu, t, off);
            if (lane >= off) t += n;
        }
        s_wtot[lane] = t;
    }
    __syncthreads();
    double incl  = s + (warp ? s_wtot[warp - 1] : 0.0);
    double total = s_wtot[31];
    double target = (double)uinit[i] * total;
    if (tid == 0) { s_pick = DB - 1; s_base = total - g_bsum[DB - 1]; }
    __syncthreads();
    if (tid < DB) {
        double excl = incl - v;
        if (excl < target && target <= incl) { s_pick = tid; s_base = excl; }
    }
    __syncthreads();
    int    tb    = s_pick;
    double resid = target - s_base;
    int sst = tb * chunk;
    int sen = min(sst + chunk, N);
    int cnt = sen - sst;
    __syncthreads();

    double dv = (tid < cnt) ? (double)g_dmin[sst + tid] : 0.0;
    double s2 = dv;
    #pragma unroll
    for (int off = 1; off < 32; off <<= 1) {
        double n = __shfl_up_sync(0xffffffffu, s2, off);
        if (lane >= off) s2 += n;
    }
    if (lane == 31) s_wtot[warp] = s2;
    __syncthreads();
    if (warp == 0) {
        double t = s_wtot[lane];
        #pragma unroll
        for (int off = 1; off < 32; off <<= 1) {
            double n = __shfl_up_sync(0xffffffffu, t, off);
            if (lane >= off) t += n;
        }
        s_wtot[lane] = t;
    }
    __syncthreads();
    double incl2 = s2 + (warp ? s_wtot[warp - 1] : 0.0);
    if (tid == 0) s_pick = cnt - 1;
    __syncthreads();
    if (tid < cnt) {
        double excl2 = incl2 - dv;
        if (excl2 < resid && resid <= incl2) s_pick = tid;
    }
    __syncthreads();
    int idx = sst + s_pick;
    if (idx > N - 1) idx = N - 1;

    if (tid < D) {
        float cv = x[(size_t)idx * D + tid];
        g_centers[i * D + tid] = cv;
        s_sq[tid] = (double)cv * (double)cv;
    }
    __syncthreads();
    for (int sft = 128; sft; sft >>= 1) {
        if (tid < sft) s_sq[tid] += s_sq[tid + sft];
        __syncthreads();
    }
    if (tid == 0) g_csq[i] = (float)s_sq[0];
}

// ---------------------------------------------------------------------------
// Persistent iteration kernel: 320 threads, 3-row interleaved mainloop,
// contiguous chunks with updater offload, generic log-tree combine.
// ---------------------------------------------------------------------------
template <int K>
__global__ void __launch_bounds__(T1) k_iter(const float* __restrict__ x,
                                             float* __restrict__ out_r,
                                             float* __restrict__ out_c,
                                             int N) {
    constexpr int G = (K <= 4) ? 4 : 8;
    __shared__ float4 s_slot[5][K * 64];
    __shared__ float  s_cntw[NW1][8];
    __shared__ double s_part[4][64][4];
    __shared__ double s_cntv;
    __shared__ double s_v[128];

    int tid  = threadIdx.x;
    int lane = tid & 31;
    int warp = tid >> 5;
    int bid  = blockIdx.x;
    int jl   = lane & (G - 1);
    int maxit = g_maxiters;

    if (maxit < 1) {
        size_t tot = (size_t)N * K;
        for (size_t i = (size_t)bid * T1 + tid; i < tot; i += (size_t)GRID1 * T1)
            out_r[i] = 0.f;
        if (bid == 0)
            for (int i = tid; i < K * D; i += T1) out_c[i] = g_centers[i];
        return;
    }

    int Cb = (N + K * OFFL + GRID1 - 1) / GRID1;
    int Cs = Cb - OFFL;
    int st0 = (bid < K) ? bid * Cs : K * Cs + (bid - K) * Cb;
    int sz  = (bid < K) ? Cs : Cb;
    int cst = min(st0, N);
    int cen = min(st0 + sz, N);

    float w_l = (jl < K) ? __ldg(&g_w[jl]) : 0.f;

    for (int t = 0; t < maxit; t++) {
        float csq_l = (jl < K) ? __ldcg(&g_csq[jl]) : 0.f;
        u64 c_pk[K][4];
        const float4* cb = (const float4*)g_centers;
        #pragma unroll
        for (int j = 0; j < K; j++) {
            float4 c0 = __ldcg(cb + j * 64 + lane);
            float4 c1 = __ldcg(cb + j * 64 + 32 + lane);
            c_pk[j][0] = pk2(c0.x, c0.y); c_pk[j][1] = pk2(c0.z, c0.w);
            c_pk[j][2] = pk2(c1.x, c1.y); c_pk[j][3] = pk2(c1.z, c1.w);
        }
        u64 acc2[K][4];
        #pragma unroll
        for (int j = 0; j < K; j++) {
            #pragma unroll
            for (int u = 0; u < 4; u++) acc2[j][u] = 0ull;
        }
        float cnt_l = 0.f;

        // ---- main pass: THREE interleaved rows within contiguous chunk ----
        int row = cst + warp;
        while (row + 2 * NW1 < cen) {
            int rA = row, rB = row + NW1, rC = row + 2 * NW1;
            const ulonglong2* xA = (const ulonglong2*)x + (size_t)rA * (D / 4);
            const ulonglong2* xB = (const ulonglong2*)x + (size_t)rB * (D / 4);
            const ulonglong2* xC = (const ulonglong2*)x + (size_t)rC * (D / 4);
            ulonglong2 vA0 = __ldg(xA + lane);
            ulonglong2 vB0 = __ldg(xB + lane);
            ulonglong2 vC0 = __ldg(xC + lane);
            ulonglong2 vA1 = __ldg(xA + lane + 32);
            ulonglong2 vB1 = __ldg(xB + lane + 32);
            ulonglong2 vC1 = __ldg(xC + lane + 32);
            float xsA = __ldg(g_xsq + rA);
            float xsB = __ldg(g_xsq + rB);
            float xsC = __ldg(g_xsq + rC);
            u64 pA0 = vA0.x, pA1 = vA0.y, pA2 = vA1.x, pA3 = vA1.y;
            u64 pB0 = vB0.x, pB1 = vB0.y, pB2 = vB1.x, pB3 = vB1.y;
            u64 pC0 = vC0.x, pC1 = vC0.y, pC2 = vC1.x, pC3 = vC1.y;
            float dpA[K], dpB[K], dpC[K];
            #pragma unroll
            for (int j = 0; j < K; j++) {
                u64 tA = mul2(pA0, c_pk[j][0]);
                u64 tB = mul2(pB0, c_pk[j][0]);
                u64 tC = mul2(pC0, c_pk[j][0]);
                tA = fma2(pA1, c_pk[j][1], tA);
                tB = fma2(pB1, c_pk[j][1], tB);
                tC = fma2(pC1, c_pk[j][1], tC);
                tA = fma2(pA2, c_pk[j][2], tA);
                tB = fma2(pB2, c_pk[j][2], tB);
                tC = fma2(pC2, c_pk[j][2], tC);
                tA = fma2(pA3, c_pk[j][3], tA);
                tB = fma2(pB3, c_pk[j][3], tB);
                tC = fma2(pC3, c_pk[j][3], tC);
                float loA, hiA, loB, hiB, loC, hiC;
                upk2(tA, loA, hiA); upk2(tB, loB, hiB); upk2(tC, loC, hiC);
                dpA[j] = loA + hiA; dpB[j] = loB + hiB; dpC[j] = loC + hiC;
            }
            #pragma unroll
            for (int m = G / 2; m; m >>= 1) {
                #pragma unroll
                for (int j = 0; j < K; j++) {
                    dpA[j] += __shfl_xor_sync(0xffffffffu, dpA[j], m);
                    dpB[j] += __shfl_xor_sync(0xffffffffu, dpB[j], m);
                    dpC[j] += __shfl_xor_sync(0xffffffffu, dpC[j], m);
                }
            }
            float myA = dpA[0], myB = dpB[0], myC = dpC[0];
            #pragma unroll
            for (int j = 1; j < K; j++) {
                bool p = (jl == j);
                myA = p ? dpA[j] : myA;
                myB = p ? dpB[j] : myB;
                myC = p ? dpC[j] : myC;
            }
            #pragma unroll
            for (int m = G; m < 32; m <<= 1) {
                myA += __shfl_xor_sync(0xffffffffu, myA, m);
                myB += __shfl_xor_sync(0xffffffffu, myB, m);
                myC += __shfl_xor_sync(0xffffffffu, myC, m);
            }

            float dA = sqrtf(fmaxf(xsA + csq_l - 2.f * myA, 1e-12f));
            float dB = sqrtf(fmaxf(xsB + csq_l - 2.f * myB, 1e-12f));
            float dC = sqrtf(fmaxf(xsC + csq_l - 2.f * myC, 1e-12f));
            float eA = w_l * __expf(ESHIFT - dA);
            float eB = w_l * __expf(ESHIFT - dB);
            float eC = w_l * __expf(ESHIFT - dC);
            float sA = eA, sB = eB, sC = eC;
            #pragma unroll
            for (int m = 1; m < G; m <<= 1) {
                sA += __shfl_xor_sync(0xffffffffu, sA, m);
                sB += __shfl_xor_sync(0xffffffffu, sB, m);
                sC += __shfl_xor_sync(0xffffffffu, sC, m);
            }
            float rvA = __fdividef(eA, sA);
            float rvB = __fdividef(eB, sB);
            float rvC = __fdividef(eC, sC);
            if (lane < K) {
                out_r[(size_t)rA * K + lane] = rvA;
                out_r[(size_t)rB * K + lane] = rvB;
                out_r[(size_t)rC * K + lane] = rvC;
            }
            cnt_l += rvA + rvB + rvC;
            #pragma unroll
            for (int j = 0; j < K; j++) {
                float rbA = __shfl_sync(0xffffffffu, rvA, j);
                float rbB = __shfl_sync(0xffffffffu, rvB, j);
                float rbC = __shfl_sync(0xffffffffu, rvC, j);
                u64 r2A = pk2(rbA, rbA);
                u64 r2B = pk2(rbB, rbB);
                u64 r2C = pk2(rbC, rbC);
                acc2[j][0] = fma2(r2A, pA0, acc2[j][0]);
                acc2[j][1] = fma2(r2A, pA1, acc2[j][1]);
                acc2[j][2] = fma2(r2A, pA2, acc2[j][2]);
                acc2[j][3] = fma2(r2A, pA3, acc2[j][3]);
                acc2[j][0] = fma2(r2B, pB0, acc2[j][0]);
                acc2[j][1] = fma2(r2B, pB1, acc2[j][1]);
                acc2[j][2] = fma2(r2B, pB2, acc2[j][2]);
                acc2[j][3] = fma2(r2B, pB3, acc2[j][3]);
                acc2[j][0] = fma2(r2C, pC0, acc2[j][0]);
                acc2[j][1] = fma2(r2C, pC1, acc2[j][1]);
                acc2[j][2] = fma2(r2C, pC2, acc2[j][2]);
                acc2[j][3] = fma2(r2C, pC3, acc2[j][3]);
            }
            row += 3 * NW1;
        }
        while (row < cen) {  // 1-2 row tail
            const ulonglong2* xr = (const ulonglong2*)x + (size_t)row * (D / 4);
            ulonglong2 v0 = __ldg(xr + lane);
            ulonglong2 v1 = __ldg(xr + lane + 32);
            float  xs = __ldg(g_xsq + row);
            u64 p0 = v0.x, p1 = v0.y, p2 = v1.x, p3 = v1.y;
            float dp[K];
            #pragma unroll
            for (int j = 0; j < K; j++) {
                u64 tt = mul2(p0, c_pk[j][0]);
                tt = fma2(p1, c_pk[j][1], tt);
                tt = fma2(p2, c_pk[j][2], tt);
                tt = fma2(p3, c_pk[j][3], tt);
                float lo, hi; upk2(tt, lo, hi);
                dp[j] = lo + hi;
            }
            #pragma unroll
            for (int m = G / 2; m; m >>= 1) {
                #pragma unroll
                for (int j = 0; j < K; j++)
                    dp[j] += __shfl_xor_sync(0xffffffffu, dp[j], m);
            }
            float myv = dp[0];
            #pragma unroll
            for (int j = 1; j < K; j++) myv = (jl == j) ? dp[j] : myv;
            #pragma unroll
            for (int m = G; m < 32; m <<= 1)
                myv += __shfl_xor_sync(0xffffffffu, myv, m);
            float dval = sqrtf(fmaxf(xs + csq_l - 2.f * myv, 1e-12f));
            float ev   = w_l * __expf(ESHIFT - dval);
            float ssum = ev;
            #pragma unroll
            for (int m = 1; m < G; m <<= 1)
                ssum += __shfl_xor_sync(0xffffffffu, ssum, m);
            float rv = __fdividef(ev, ssum);
            if (lane < K) out_r[(size_t)row * K + lane] = rv;
            cnt_l += rv;
            #pragma unroll
            for (int j = 0; j < K; j++) {
                float rb = __shfl_sync(0xffffffffu, rv, j);
                u64 r2 = pk2(rb, rb);
                acc2[j][0] = fma2(r2, p0, acc2[j][0]);
                acc2[j][1] = fma2(r2, p1, acc2[j][1]);
                acc2[j][2] = fma2(r2, p2, acc2[j][2]);
                acc2[j][3] = fma2(r2, p3, acc2[j][3]);
            }
            row += NW1;
        }

        // ---- per-warp counts ----
        if (lane < K) s_cntw[warp][lane] = cnt_l;

        // ---- unpack accumulators ----
        float a[K][8];
        #pragma unroll
        for (int j = 0; j < K; j++) {
            upk2(acc2[j][0], a[j][0], a[j][1]);
            upk2(acc2[j][1], a[j][2], a[j][3]);
            upk2(acc2[j][2], a[j][4], a[j][5]);
            upk2(acc2[j][3], a[j][6], a[j][7]);
        }

        // ---- generic log-tree combine over NW1=10 warps ----
        #pragma unroll
        for (int step = 8; step >= 1; step >>= 1) {
            if (warp >= step && warp < 2 * step && warp < NW1) {
                float4* dst = s_slot[warp - step >= 5 ? 4 : warp - step];  // safe idx
                // NOTE: for NW1=10, max slot index = min(NW1,2*step)-step-1 <= 4
                dst = s_slot[warp - step];
                #pragma unroll
                for (int j = 0; j < K; j++) {
                    dst[j * 64 + lane]      = make_float4(a[j][0], a[j][1], a[j][2], a[j][3]);
                    dst[j * 64 + 32 + lane] = make_float4(a[j][4], a[j][5], a[j][6], a[j][7]);
                }
            }
            __syncthreads();
            if (warp < step && warp + step < NW1) {
                const float4* src = s_slot[warp];
                #pragma unroll
                for (int j = 0; j < K; j++) {
                    float4 v0 = src[j * 64 + lane];
                    float4 v1 = src[j * 64 + 32 + lane];
                    a[j][0] += v0.x; a[j][1] += v0.y; a[j][2] += v0.z; a[j][3] += v0.w;
                    a[j][4] += v1.x; a[j][5] += v1.y; a[j][6] += v1.z; a[j][7] += v1.w;
                }
            }
            __syncthreads();
        }
        if (warp == 0) {
            float4* Pb = (float4*)(g_P + (size_t)bid * (KMAX * D));
            #pragma unroll
            for (int j = 0; j < K; j++) {
                Pb[j * 64 + lane]      = make_float4(a[j][0], a[j][1], a[j][2], a[j][3]);
                Pb[j * 64 + 32 + lane] = make_float4(a[j][4], a[j][5], a[j][6], a[j][7]);
            }
        }
        if (tid < K) {
            float s = 0.f;
            #pragma unroll
            for (int w = 0; w < NW1; w++) s += s_cntw[w][tid];
            g_Pc[bid * KMAX + tid] = s;
        }

        // ---- barrier 1 (flag-based): stamp own flag; only updaters wait ----
        __syncthreads();
        __threadfence();
        if (tid == 0) st_cg_i32(&g_flag_main[bid * FPAD], t + 1);

        if (bid < K) {
            if (warp == 0) {
                int need = t + 1;
                bool done_poll = false;
                while (!done_poll) {
                    bool ok = true;
                    for (int p = lane; p < GRID1; p += 32)
                        ok &= (ld_cg_i32(&g_flag_main[p * FPAD]) >= need);
                    done_poll = __all_sync(0xffffffffu, ok);
                    if (!done_poll) __nanosleep(64);
                }
                __threadfence();
            }
            __syncthreads();

            int j = bid;
            if (warp == 9) {
                double c = 0.0;
                for (int p = lane; p < GRID1; p += 32)
                    c += (double)__ldcg(&g_Pc[p * KMAX + j]);
                #pragma unroll
                for (int m = 16; m; m >>= 1)
                    c += __shfl_xor_sync(0xffffffffu, c, m);
                if (lane == 0) s_cntv = c;
            }
            if (tid < 256) {
                int g = tid >> 6, i4 = tid & 63;
                int pst = g * 37;
                int pen = min(GRID1, pst + 37);
                const float4* base = (const float4*)g_P + (size_t)j * (D / 4) + i4;
                const int S4 = KMAX * D / 4;
                double dx = 0.0, dy = 0.0, dz = 0.0, dw = 0.0;
                int p = pst;
                for (; p + 8 <= pen; p += 8) {
                    float4 v0 = __ldcg(base + (size_t)(p + 0) * S4);
                    float4 v1 = __ldcg(base + (size_t)(p + 1) * S4);
                    float4 v2 = __ldcg(base + (size_t)(p + 2) * S4);
                    float4 v3 = __ldcg(base + (size_t)(p + 3) * S4);
                    float4 v4 = __ldcg(base + (size_t)(p + 4) * S4);
                    float4 v5 = __ldcg(base + (size_t)(p + 5) * S4);
                    float4 v6 = __ldcg(base + (size_t)(p + 6) * S4);
                    float4 v7 = __ldcg(base + (size_t)(p + 7) * S4);
                    dx += (((double)v0.x + (double)v1.x) + ((double)v2.x + (double)v3.x))
                        + (((double)v4.x + (double)v5.x) + ((double)v6.x + (double)v7.x));
                    dy += (((double)v0.y + (double)v1.y) + ((double)v2.y + (double)v3.y))
                        + (((double)v4.y + (double)v5.y) + ((double)v6.y + (double)v7.y));
                    dz += (((double)v0.z + (double)v1.z) + ((double)v2.z + (double)v3.z))
                        + (((double)v4.z + (double)v5.z) + ((double)v6.z + (double)v7.z));
                    dw += (((double)v0.w + (double)v1.w) + ((double)v2.w + (double)v3.w))
                        + (((double)v4.w + (double)v5.w) + ((double)v6.w + (double)v7.w));
                }
                for (; p < pen; p++) {
                    float4 v = __ldcg(base + (size_t)p * S4);
                    dx += (double)v.x; dy += (double)v.y;
                    dz += (double)v.z; dw += (double)v.w;
                }
                s_part[g][i4][0] = dx; s_part[g][i4][1] = dy;
                s_part[g][i4][2] = dz; s_part[g][i4][3] = dw;
            }
            __syncthreads();
            if (tid < 64) {
                double cnt = s_cntv;
                double sx = (s_part[0][tid][0] + s_part[1][tid][0])
                          + (s_part[2][tid][0] + s_part[3][tid][0]);
                double sy = (s_part[0][tid][1] + s_part[1][tid][1])
                          + (s_part[2][tid][1] + s_part[3][tid][1]);
                double sz = (s_part[0][tid][2] + s_part[1][tid][2])
                          + (s_part[2][tid][2] + s_part[3][tid][2]);
                double sw = (s_part[0][tid][3] + s_part[1][tid][3])
                          + (s_part[2][tid][3] + s_part[3][tid][3]);
                float n0 = (float)(sx / cnt), n1 = (float)(sy / cnt);
                float n2 = (float)(sz / cnt), n3 = (float)(sw / cnt);
                int e4 = j * (D / 4) + tid;
                ((float4*)g_centers)[e4] = make_float4(n0, n1, n2, n3);
                float4 pv = ((float4*)g_prev)[e4];
                ((float4*)g_prev)[e4] = make_float4(n0, n1, n2, n3);
                double d0 = (double)(n0 - pv.x), d1 = (double)(n1 - pv.y);
                double d2 = (double)(n2 - pv.z), d3 = (double)(n3 - pv.w);
                s_v[tid]      = (d0 * d0 + d1 * d1) + (d2 * d2 + d3 * d3);
                s_v[64 + tid] = ((double)n0 * n0 + (double)n1 * n1)
                              + ((double)n2 * n2 + (double)n3 * n3);
            }
            __syncthreads();
            if (warp == 0) {
                double aa = s_v[lane] + s_v[lane + 32];
                #pragma unroll
                for (int m = 16; m; m >>= 1)
                    aa += __shfl_xor_sync(0xffffffffu, aa, m);
                if (lane == 0) g_shiftp[j] = aa;
            } else if (warp == 1) {
                double aa = s_v[64 + lane] + s_v[96 + lane];
                #pragma unroll
                for (int m = 16; m; m >>= 1)
                    aa += __shfl_xor_sync(0xffffffffu, aa, m);
                if (lane == 0) g_csq[j] = (float)aa;
            }
            __syncthreads();
            __threadfence();
            if (tid == 0) st_cg_i32(&g_flag_upd[j * FPAD], t + 1);
        }

        // ---- barrier 2 (flag-based): everyone waits for the K upd flags ----
        if (warp == 0) {
            int need = t + 1;
            bool done_poll = false;
            while (!done_poll) {
                bool ok = (lane >= K) || (ld_cg_i32(&g_flag_upd[lane * FPAD]) >= need);
                done_poll = __all_sync(0xffffffffu, ok);
                if (!done_poll) __nanosleep(64);
            }
            __threadfence();
        }
        __syncthreads();

        double sh = 0.0;
        #pragma unroll
        for (int j = 0; j < K; j++) sh += __ldcg(&g_shiftp[j]);
        if (sqrt(sh) < TOLV) break;
    }

    if (bid == 0)
        for (int i = tid; i < K * D; i += T1) out_c[i] = __ldcg(&g_centers[i]);
}

// ---------------------------------------------------------------------------
extern "C" void kernel_launch(void* const* d_in, const int* in_sizes, int n_in,
                              void* d_out, int out_size) {
    const float* x      = (const float*)d_in[0];
    const float* logits = (const float*)d_in[1];
    const float* gumbel = (const float*)d_in[2];
    const float* uinit  = (const float*)d_in[3];
    const int*   maxit  = (const int*)d_in[4];

    int N = in_sizes[0] / D;
    int k = out_size / (N + D);
    if (k < 1) k = 1;
    if (k > KMAX) k = KMAX;

    float* out_c = (float*)d_out;
    float* out_r = out_c + (size_t)k * D;

    k_init<<<1, 256>>>(x, logits, gumbel, uinit, maxit, N);
    if (k == 1) {
        k_xsq<<<DB, TM>>>(x, N);
    } else {
        for (int i = 1; i < k; i++) {
            k_dmin<<<DB, TM>>>(x, N, i);           // pass 1 also fills g_xsq
            k_select<<<1, 1024>>>(x, uinit, N, i);
        }
    }
    switch (k) {
        case 1: k_iter<1><<<GRID1, T1>>>(x, out_r, out_c, N); break;
        case 2: k_iter<2><<<GRID1, T1>>>(x, out_r, out_c, N); break;
        case 3: k_iter<3><<<GRID1, T1>>>(x, out_r, out_c, N); break;
        case 4: k_iter<4><<<GRID1, T1>>>(x, out_r, out_c, N); break;
        case 5: k_iter<5><<<GRID1, T1>>>(x, out_r, out_c, N); break;
        default: k_iter<6><<<GRID1, T1>>>(x, out_r, out_c, N); break;
    }
}